// round 14
// baseline (speedup 1.0000x reference)
#include <cuda_runtime.h>
#include <cstdint>

// x:[B=16, T=512, F=32, CI=128]  w:[F, CO=128, CI=128, K=3]  bias:[F, CO]
// y[b,t,f,o] = sum_{k,i} x[b, t-4+2k, f, i] * w[f,o,i,k] + bias[f,o]
//
// NOTE: this toolchain emits plain compute_103 PTX -> tcgen05/TMEM ('a'-gated)
// do NOT compile. Fastest available tensor path is mma.sync.tf32 + ldmatrix.

#define TT   512
#define FF   32
#define CIN  128
#define COUT 128

#define PA 20                 // A smem pitch (words): rows start at all 32 banks -> LDSM conflict-free
#define PB 52                 // B smem pitch (words): 52 % 32 == 20, same conflict-free pattern
#define A_WORDS (132*PA)      // 132 t-rows (t0-4 .. t0+127) x 16 ci
#define B_WORDS (128*PB)      // 128 co rows x 48 words (3 taps x 16 ci)
#define SMEM_BYTES ((2*A_WORDS + 2*B_WORDS)*4)   // 74368 B double-buffered -> 2 CTAs/SM

// Pre-transformed weights: [f][co][cc=8][k=3][ci16] tf32 bits (one 48-word row per (co, chunk))
__device__ uint32_t g_wTB[(size_t)FF * COUT * 384];

__device__ __forceinline__ uint32_t f2tf32(float f) {
    uint32_t r; asm("cvt.rna.tf32.f32 %0, %1;" : "=r"(r) : "f"(f)); return r;
}

// ---------------- prologue: w[f][o][ci][k] fp32 -> g_wTB[f][o][cc][k][ci16] tf32 ----------------
__global__ __launch_bounds__(256)
void reformat_w(const float* __restrict__ w)
{
    __shared__ uint32_t S[16 * 385];       // [16 o][384 j], pitch 385
    const int f = blockIdx.x, o0 = blockIdx.y * 16;
    const int warp = threadIdx.x >> 5, lane = threadIdx.x & 31;
    const float* wf = w + ((size_t)f * COUT + o0) * (CIN * 3);
    for (int oo = warp; oo < 16; oo += 8) {            // coalesced: 384 contiguous floats / row
        const float* row = wf + (size_t)oo * (CIN * 3);
        for (int j = lane; j < 384; j += 32) S[oo * 385 + j] = f2tf32(row[j]);
    }
    __syncthreads();
    uint32_t* out = g_wTB + ((size_t)f * COUT + o0) * 384;
    const int o = threadIdx.x & 15, p0 = threadIdx.x >> 4;
    for (int p = p0; p < 384; p += 16) {               // p = cc*48 + k*16 + ci
        const int cc = p / 48, rem = p % 48;
        const int k = rem >> 4, ci = rem & 15;
        out[(size_t)o * 384 + p] = S[o * 385 + (cc * 16 + ci) * 3 + k];
    }
}

// ---------------- async-copy helpers ----------------
__device__ __forceinline__ void cp16(uint32_t dst, const void* src, uint32_t sz) {
    asm volatile("cp.async.cg.shared.global [%0], [%1], 16, %2;\n" :: "r"(dst), "l"(src), "r"(sz));
}
__device__ __forceinline__ void cp_commit() { asm volatile("cp.async.commit_group;\n"); }
template<int N> __device__ __forceinline__ void cp_wait() {
    asm volatile("cp.async.wait_group %0;\n" :: "n"(N));
}

#define MMA_TF32(d, A0,A1,A2,A3, B0,B1)                                      \
    asm volatile("mma.sync.aligned.m16n8k8.row.col.f32.tf32.tf32.f32 "       \
                 "{%0,%1,%2,%3}, {%4,%5,%6,%7}, {%8,%9}, {%0,%1,%2,%3};"     \
                 : "+f"((d)[0]), "+f"((d)[1]), "+f"((d)[2]), "+f"((d)[3])    \
                 : "r"(A0), "r"(A1), "r"(A2), "r"(A3), "r"(B0), "r"(B1))

#define LDSM_X4(R0,R1,R2,R3, addr)                                           \
    asm volatile("ldmatrix.sync.aligned.m8n8.x4.shared.b16 {%0,%1,%2,%3}, [%4];" \
                 : "=r"(R0), "=r"(R1), "=r"(R2), "=r"(R3) : "r"(addr))

#define LDSM_X2(R0,R1, addr)                                                 \
    asm volatile("ldmatrix.sync.aligned.m8n8.x2.shared.b16 {%0,%1}, [%2];"   \
                 : "=r"(R0), "=r"(R1) : "r"(addr))

// ---------------- main kernel ----------------
// CTA: 256 thr (8 warps as 4M x 2N), tile = 128 t-rows x 128 co; warp = 32M x 64N.
// K = 384 in 8 chunks of 16 ci; x tile rows t0-4..t0+127 so taps are row offsets +0/+2/+4.
// Fragments fed by ldmatrix: A x4 (16 rows x 8 ci), B x2 on [co][ci]-major smem.
__global__ __launch_bounds__(256, 2)
void conv_mma_kernel(const float* __restrict__ x,
                     const float* __restrict__ bias,
                     float* __restrict__ y)
{
    extern __shared__ __align__(16) char smem_c[];
    uint32_t* smemw = reinterpret_cast<uint32_t*>(smem_c);
    const int tid = threadIdx.x;
    const int t0 = blockIdx.x * 128, b = blockIdx.y, f = blockIdx.z;
    const int lane = tid & 31, warp = tid >> 5;
    const int wm = (warp & 3) * 32, wn = (warp >> 2) * 64;
    const int group = lane >> 2, tig = lane & 3;
    const uint32_t sbase = (uint32_t)__cvta_generic_to_shared(smemw);

    // --- staging plan: A (x tile) ---
    const char* xrow0 = (const char*)(x + ((size_t)b * TT) * (FF * CIN) + (size_t)f * CIN);
    uint32_t a_dst[3], a_off[3], a_sz[3];
    int a_cnt = 0;
    for (int i = tid; i < 528; i += 256) {             // 132 rows x 4 16B-chunks
        const int r = i >> 2, seg = i & 3;
        const int t = t0 - 4 + r;
        a_dst[a_cnt] = (uint32_t)((r * PA + seg * 4) * 4);
        a_off[a_cnt] = (uint32_t)((t < 0 ? 0 : t) * (FF * CIN) * 4 + seg * 16);
        a_sz[a_cnt]  = (t >= 0) ? 16u : 0u;            // causal pad: zero-fill
        a_cnt++;
    }
    // --- staging plan: B (weights, [co][48w] rows) : 128 rows x 12 16B-chunks = 6/thread ---
    const char* wfB = (const char*)(g_wTB + (size_t)f * COUT * 384);
    uint32_t b_dst[6], b_off[6];
    #pragma unroll
    for (int j = 0; j < 6; j++) {
        const int i = tid + j * 256;
        const int row = i / 12, seg = i % 12;
        b_dst[j] = (uint32_t)((row * PB + seg * 4) * 4);
        b_off[j] = (uint32_t)((row * 384 + seg * 4) * 4);   // + cc*192 bytes per chunk
    }
    auto prefetch = [&](int cc, int d) {
        const uint32_t aB = sbase + (uint32_t)(d * A_WORDS * 4);
        const uint32_t bB = sbase + (uint32_t)((2 * A_WORDS + d * B_WORDS) * 4);
        const uint32_t cA = (uint32_t)(cc * 16 * 4);
        const uint32_t cB = (uint32_t)(cc * 192);
        for (int j = 0; j < a_cnt; j++) cp16(aB + a_dst[j], xrow0 + a_off[j] + cA, a_sz[j]);
        #pragma unroll
        for (int j = 0; j < 6; j++) cp16(bB + b_dst[j], wfB + b_off[j] + cB, 16u);
    };

    // --- ldmatrix per-thread base offsets ---
    // A x4: thread i supplies row of block q=i>>3: rows (q&1)*8 + (i&7), col-half (q>>1)*4
    const int q = lane >> 3, r5 = lane & 7;
    const uint32_t a_tho = (uint32_t)(((wm + (q & 1) * 8 + r5) * PA + (q >> 1) * 4) * 4);
    // B x2: thread i<16 supplies row (i&7) of block (i>>3): col-half ((i>>3)&1)*4
    const uint32_t b_tho = (uint32_t)(((wn + r5) * PB + (q & 1) * 4) * 4);

    float acc[2][8][4];
    #pragma unroll
    for (int i = 0; i < 2; i++)
        #pragma unroll
        for (int j = 0; j < 8; j++)
            #pragma unroll
            for (int p = 0; p < 4; p++) acc[i][j][p] = 0.f;

    prefetch(0, 0); cp_commit();

    #pragma unroll 1
    for (int cc = 0; cc < 8; ++cc) {
        const int d = cc & 1;
        if (cc < 7) { prefetch(cc + 1, d ^ 1); cp_commit(); }
        if (cc < 7) cp_wait<1>(); else cp_wait<0>();
        __syncthreads();

        const uint32_t Ad = sbase + (uint32_t)(d * A_WORDS * 4) + a_tho;
        const uint32_t Bd = sbase + (uint32_t)((2 * A_WORDS + d * B_WORDS) * 4) + b_tho;

        #pragma unroll
        for (int k = 0; k < 3; k++) {        // taps: A rows shift by +2 per tap
            #pragma unroll
            for (int kh = 0; kh < 2; kh++) { // two K=8 halves of the 16-ci chunk
                uint32_t a[8];
                LDSM_X4(a[0], a[1], a[2], a[3], Ad + (uint32_t)(((2 * k) * PA + kh * 8) * 4));
                LDSM_X4(a[4], a[5], a[6], a[7], Ad + (uint32_t)(((16 + 2 * k) * PA + kh * 8) * 4));
                #pragma unroll
                for (int nt = 0; nt < 8; nt++) {
                    uint32_t b0v, b1v;
                    LDSM_X2(b0v, b1v, Bd + (uint32_t)((nt * 8 * PB + k * 16 + kh * 8) * 4));
                    MMA_TF32(acc[0][nt], a[0], a[1], a[2], a[3], b0v, b1v);  // rows wm..wm+15
                    MMA_TF32(acc[1][nt], a[4], a[5], a[6], a[7], b0v, b1v);  // rows wm+16..wm+31
                }
            }
        }
        __syncthreads();
    }

    // --- epilogue: bias + fp32 stores (float2) ---
    const float* bf = bias + (size_t)f * COUT;
    const int r0 = t0 + wm + group;
    #pragma unroll
    for (int nt = 0; nt < 8; nt++) {
        const int n = wn + nt * 8 + tig * 2;
        const float bx = bf[n], by = bf[n + 1];
        #pragma unroll
        for (int rb = 0; rb < 2; rb++) {
            const int r = r0 + rb * 16;
            const size_t o0i = (((size_t)b * TT + r) * FF + f) * (size_t)COUT + n;
            const size_t o1i = (((size_t)b * TT + r + 8) * FF + f) * (size_t)COUT + n;
            *reinterpret_cast<float2*>(y + o0i) = make_float2(acc[rb][nt][0] + bx, acc[rb][nt][1] + by);
            *reinterpret_cast<float2*>(y + o1i) = make_float2(acc[rb][nt][2] + bx, acc[rb][nt][3] + by);
        }
    }
}

extern "C" void kernel_launch(void* const* d_in, const int* in_sizes, int n_in,
                              void* d_out, int out_size)
{
    const float* x    = (const float*)d_in[0];  // [16,512,32,128]
    const float* w    = (const float*)d_in[1];  // [32,128,128,3]
    const float* bias = (const float*)d_in[2];  // [32,128]
    float* y = (float*)d_out;

    cudaFuncSetAttribute(conv_mma_kernel,
                         cudaFuncAttributeMaxDynamicSharedMemorySize, SMEM_BYTES);

    reformat_w<<<dim3(FF, 8), 256>>>(w);
    conv_mma_kernel<<<dim3(TT / 128, 16 /*B*/, FF), 256, SMEM_BYTES>>>(x, bias, y);
}

// round 16
// speedup vs baseline: 1.0156x; 1.0156x over previous
#include <cuda_runtime.h>
#include <cstdint>

// x:[B=16, T=512, F=32, CI=128]  w:[F, CO=128, CI=128, K=3]  bias:[F, CO]
// y[b,t,f,o] = sum_{k,i} x[b, t-4+2k, f, i] * w[f,o,i,k] + bias[f,o]
//
// NOTE: toolchain emits plain compute_103 PTX -> tcgen05/TMEM ('a'-gated) do not
// compile. Tensor path = mma.sync.tf32 + ldmatrix. Floor: ~85us tensor-busy.

#define TT   512
#define FF   32
#define CIN  128
#define COUT 128

#define PA 20                    // A pitch (words): 20 mod 32 -> LDSM conflict-free
#define PB 52                    // B pitch (words): 52 mod 32 = 20 -> conflict-free
#define A_WORDS (132*PA)         // 132 t-rows (t0-4 .. t0+127) x 16 ci
#define B_WORDS (128*PB)         // 128 co rows x 48 words (3 taps x 16 ci)
#define STAGE_WORDS (A_WORDS + B_WORDS)        // 9296 words = 37184 B
#define SMEM_BYTES (3*STAGE_WORDS*4)           // 111552 B, 3-stage ring -> 2 CTAs/SM (223KB/228KB)

// Pre-transformed weights: [f][co][cc=8][k=3][ci16] tf32 bits
__device__ uint32_t g_wTB[(size_t)FF * COUT * 384];

__device__ __forceinline__ uint32_t f2tf32(float f) {
    uint32_t r; asm("cvt.rna.tf32.f32 %0, %1;" : "=r"(r) : "f"(f)); return r;
}

// ---------------- prologue: w[f][o][ci][k] fp32 -> g_wTB[f][o][cc][k][ci16] tf32 ----------------
__global__ __launch_bounds__(256)
void reformat_w(const float* __restrict__ w)
{
    __shared__ uint32_t S[16 * 385];
    const int f = blockIdx.x, o0 = blockIdx.y * 16;
    const int warp = threadIdx.x >> 5, lane = threadIdx.x & 31;
    const float* wf = w + ((size_t)f * COUT + o0) * (CIN * 3);
    for (int oo = warp; oo < 16; oo += 8) {
        const float* row = wf + (size_t)oo * (CIN * 3);
        for (int j = lane; j < 384; j += 32) S[oo * 385 + j] = f2tf32(row[j]);
    }
    __syncthreads();
    uint32_t* out = g_wTB + ((size_t)f * COUT + o0) * 384;
    const int o = threadIdx.x & 15, p0 = threadIdx.x >> 4;
    for (int p = p0; p < 384; p += 16) {               // p = cc*48 + k*16 + ci
        const int cc = p / 48, rem = p % 48;
        const int k = rem >> 4, ci = rem & 15;
        out[(size_t)o * 384 + p] = S[o * 385 + (cc * 16 + ci) * 3 + k];
    }
}

// ---------------- async-copy helpers ----------------
__device__ __forceinline__ void cp16(uint32_t dst, const void* src, uint32_t sz) {
    asm volatile("cp.async.cg.shared.global [%0], [%1], 16, %2;\n" :: "r"(dst), "l"(src), "r"(sz));
}
__device__ __forceinline__ void cp_commit() { asm volatile("cp.async.commit_group;\n"); }
template<int N> __device__ __forceinline__ void cp_wait() {
    asm volatile("cp.async.wait_group %0;\n" :: "n"(N));
}

#define MMA_TF32(d, A0,A1,A2,A3, B0,B1)                                      \
    asm volatile("mma.sync.aligned.m16n8k8.row.col.f32.tf32.tf32.f32 "       \
                 "{%0,%1,%2,%3}, {%4,%5,%6,%7}, {%8,%9}, {%0,%1,%2,%3};"     \
                 : "+f"((d)[0]), "+f"((d)[1]), "+f"((d)[2]), "+f"((d)[3])    \
                 : "r"(A0), "r"(A1), "r"(A2), "r"(A3), "r"(B0), "r"(B1))

#define LDSM_X4(R0,R1,R2,R3, addr)                                           \
    asm volatile("ldmatrix.sync.aligned.m8n8.x4.shared.b16 {%0,%1,%2,%3}, [%4];" \
                 : "=r"(R0), "=r"(R1), "=r"(R2), "=r"(R3) : "r"(addr))

// ---------------- main kernel ----------------
// CTA: 256 thr (8 warps as 4M x 2N), tile = 128 t-rows x 128 co; warp = 32M x 64N.
// K = 384 in 8 chunks of 16 ci; A rows t0-4..t0+127 so taps are row offsets +0/+2/+4.
// 3-stage smem ring, ONE __syncthreads per chunk, 2-deep load lookahead.
__global__ __launch_bounds__(256, 2)
void conv_mma_kernel(const float* __restrict__ x,
                     const float* __restrict__ bias,
                     float* __restrict__ y)
{
    extern __shared__ __align__(16) char smem_c[];
    uint32_t* smemw = reinterpret_cast<uint32_t*>(smem_c);
    const int tid = threadIdx.x;
    const int t0 = blockIdx.x * 128, b = blockIdx.y, f = blockIdx.z;
    const int lane = tid & 31, warp = tid >> 5;
    const int wm = (warp & 3) * 32, wn = (warp >> 2) * 64;
    const int group = lane >> 2, tig = lane & 3;
    const uint32_t sbase = (uint32_t)__cvta_generic_to_shared(smemw);

    // --- staging plan: A (x tile): 132 rows x 4 16B-chunks; causal pad -> zero-fill ---
    const char* xrow0 = (const char*)(x + ((size_t)b * TT) * (FF * CIN) + (size_t)f * CIN);
    uint32_t a_dst[3], a_off[3], a_sz[3];
    int a_cnt = 0;
    for (int i = tid; i < 528; i += 256) {
        const int r = i >> 2, seg = i & 3;
        const int t = t0 - 4 + r;
        a_dst[a_cnt] = (uint32_t)((r * PA + seg * 4) * 4);
        a_off[a_cnt] = (uint32_t)((t < 0 ? 0 : t) * (FF * CIN) * 4 + seg * 16);
        a_sz[a_cnt]  = (t >= 0) ? 16u : 0u;
        a_cnt++;
    }
    // --- staging plan: B: 128 rows x 12 16B-chunks = 6/thread, fully coalesced ---
    const char* wfB = (const char*)(g_wTB + (size_t)f * COUT * 384);
    uint32_t b_dst[6], b_off[6];
    #pragma unroll
    for (int j = 0; j < 6; j++) {
        const int i = tid + j * 256;
        const int row = i / 12, seg = i % 12;
        b_dst[j] = (uint32_t)((row * PB + seg * 4) * 4);
        b_off[j] = (uint32_t)((row * 384 + seg * 4) * 4);   // + cc*192 bytes per chunk
    }
    auto prefetch = [&](int cc, int m) {
        const uint32_t aB = sbase + (uint32_t)(m * STAGE_WORDS * 4);
        const uint32_t bB = aB + (uint32_t)(A_WORDS * 4);
        const uint32_t cA = (uint32_t)(cc * 16 * 4);
        const uint32_t cB = (uint32_t)(cc * 192);
        for (int j = 0; j < a_cnt; j++) cp16(aB + a_dst[j], xrow0 + a_off[j] + cA, a_sz[j]);
        #pragma unroll
        for (int j = 0; j < 6; j++) cp16(bB + b_dst[j], wfB + b_off[j] + cB, 16u);
    };

    // --- ldmatrix per-thread base offsets (q = lane>>3 selects the 8x8 matrix) ---
    const int q = lane >> 3, r5 = lane & 7;
    // A x4: mats = {rows+0 left16B, rows+0 right16B, rows+8 left, rows+8 right}
    const uint32_t a_tho = (uint32_t)(((wm + (q & 1) * 8 + r5) * PA + (q >> 1) * 4) * 4);
    // B x4: mats = {blk nt left, blk nt right, blk nt+1 left, blk nt+1 right}
    const uint32_t b_tho = (uint32_t)(((wn + (q >> 1) * 8 + r5) * PB + (q & 1) * 4) * 4);

    float acc[2][8][4];
    #pragma unroll
    for (int i = 0; i < 2; i++)
        #pragma unroll
        for (int j = 0; j < 8; j++)
            #pragma unroll
            for (int p = 0; p < 4; p++) acc[i][j][p] = 0.f;

    prefetch(0, 0); cp_commit();
    prefetch(1, 1); cp_commit();

    #pragma unroll 1
    for (int cc = 0; cc < 8; ++cc) {
        const int m = cc % 3;
        if (cc < 7) cp_wait<1>(); else cp_wait<0>();   // chunk cc landed (cc+1 may be in flight)
        __syncthreads();                                // all warps done with cc-1; cc visible
        if (cc + 2 < 8) { prefetch(cc + 2, (cc + 2) % 3); cp_commit(); }  // buf (cc-1)%3, just freed

        const uint32_t Ad = sbase + (uint32_t)(m * STAGE_WORDS * 4) + a_tho;
        const uint32_t Bd = sbase + (uint32_t)(m * STAGE_WORDS * 4 + A_WORDS * 4) + b_tho;

        #pragma unroll
        for (int k = 0; k < 3; k++) {        // taps: A rows shift by +2 per tap
            #pragma unroll
            for (int kh = 0; kh < 2; kh++) { // two K=8 halves of the 16-ci chunk
                uint32_t a[8];
                LDSM_X4(a[0], a[1], a[2], a[3], Ad + (uint32_t)(((2 * k) * PA + kh * 8) * 4));
                LDSM_X4(a[4], a[5], a[6], a[7], Ad + (uint32_t)(((16 + 2 * k) * PA + kh * 8) * 4));
                #pragma unroll
                for (int ntp = 0; ntp < 4; ntp++) {     // pairs of n-tiles
                    uint32_t b0v, b1v, b2v, b3v;
                    LDSM_X4(b0v, b1v, b2v, b3v,
                            Bd + (uint32_t)((ntp * 16 * PB + k * 16 + kh * 8) * 4));
                    MMA_TF32(acc[0][2 * ntp],     a[0], a[1], a[2], a[3], b0v, b1v);
                    MMA_TF32(acc[1][2 * ntp],     a[4], a[5], a[6], a[7], b0v, b1v);
                    MMA_TF32(acc[0][2 * ntp + 1], a[0], a[1], a[2], a[3], b2v, b3v);
                    MMA_TF32(acc[1][2 * ntp + 1], a[4], a[5], a[6], a[7], b2v, b3v);
                }
            }
        }
    }

    // --- epilogue: bias + fp32 stores (float2) ---
    const float* bf = bias + (size_t)f * COUT;
    const int r0 = t0 + wm + group;
    #pragma unroll
    for (int nt = 0; nt < 8; nt++) {
        const int n = wn + nt * 8 + tig * 2;
        const float bx = bf[n], by = bf[n + 1];
        #pragma unroll
        for (int rb = 0; rb < 2; rb++) {
            const int r = r0 + rb * 16;
            const size_t o0i = (((size_t)b * TT + r) * FF + f) * (size_t)COUT + n;
            const size_t o1i = (((size_t)b * TT + r + 8) * FF + f) * (size_t)COUT + n;
            *reinterpret_cast<float2*>(y + o0i) = make_float2(acc[rb][nt][0] + bx, acc[rb][nt][1] + by);
            *reinterpret_cast<float2*>(y + o1i) = make_float2(acc[rb][nt][2] + bx, acc[rb][nt][3] + by);
        }
    }
}

extern "C" void kernel_launch(void* const* d_in, const int* in_sizes, int n_in,
                              void* d_out, int out_size)
{
    const float* x    = (const float*)d_in[0];  // [16,512,32,128]
    const float* w    = (const float*)d_in[1];  // [32,128,128,3]
    const float* bias = (const float*)d_in[2];  // [32,128]
    float* y = (float*)d_out;

    cudaFuncSetAttribute(conv_mma_kernel,
                         cudaFuncAttributeMaxDynamicSharedMemorySize, SMEM_BYTES);

    reformat_w<<<dim3(FF, 8), 256>>>(w);
    conv_mma_kernel<<<dim3(TT / 128, 16 /*B*/, FF), 256, SMEM_BYTES>>>(x, bias, y);
}